// round 1
// baseline (speedup 1.0000x reference)
#include <cuda_runtime.h>
#include <cstdint>
#include <cstddef>

// Problem dims (fixed by setup_inputs)
#define B_  2
#define S_  2048
#define E_  512
#define HN  8
#define DH  64          // E_/HN
#define HBLK (256*E_)   // elements per head block inside the (S,E) projection

// Scratch (no cudaMalloc allowed) — 3 x 8MB fp32
__device__ float g_QP[B_*S_*E_];
__device__ float g_KP[B_*S_*E_];
__device__ float g_VP[B_*S_*E_];
__device__ int   g_mask_nonzero;

__device__ __forceinline__ uint32_t f2tf(float f) {
    uint32_t u;
    asm("cvt.rna.tf32.f32 %0, %1;" : "=r"(u) : "f"(f));
    return u;
}

__device__ __forceinline__ void mma8(float (&c)[4],
    uint32_t a0, uint32_t a1, uint32_t a2, uint32_t a3,
    uint32_t b0, uint32_t b1)
{
    asm volatile(
        "mma.sync.aligned.m16n8k8.row.col.f32.tf32.tf32.f32 "
        "{%0,%1,%2,%3}, {%4,%5,%6,%7}, {%8,%9}, {%0,%1,%2,%3};\n"
        : "+f"(c[0]), "+f"(c[1]), "+f"(c[2]), "+f"(c[3])
        : "r"(a0), "r"(a1), "r"(a2), "r"(a3), "r"(b0), "r"(b1));
}

// ---------------------------------------------------------------------------
// Mask scan: set flag iff any mask element is nonzero (mask is all-zero for
// this input; keeping the check makes the kernel correct for any mask).
// ---------------------------------------------------------------------------
__global__ void clear_flag_kernel() { g_mask_nonzero = 0; }

__global__ void scan_mask_kernel(const float* __restrict__ mask) {
    int stride = gridDim.x * blockDim.x;
    int i = blockIdx.x * blockDim.x + threadIdx.x;
    const int n4 = (S_*S_) >> 2;
    const float4* m4 = (const float4*)mask;
    int f = 0;
    for (; i < n4; i += stride) {
        float4 t = m4[i];
        if (t.x != 0.f || t.y != 0.f || t.z != 0.f || t.w != 0.f) f = 1;
    }
    if (f) g_mask_nonzero = 1;
}

// ---------------------------------------------------------------------------
// Projection GEMM:  P[m,n] = sum_k X[m,k] * W[n,k] + bias[n]
// M=4096 (B*S), N=512, K=512.  blockIdx.z selects {Q,K,V}.
// Block tile 128x64x32, 256 threads = 8 warps (4 m x 2 n), warp tile 32x32.
// tf32 mma m16n8k8, fp32 accumulate.
// ---------------------------------------------------------------------------
__global__ __launch_bounds__(256) void proj_kernel(
    const float* __restrict__ q, const float* __restrict__ k, const float* __restrict__ v,
    const float* __restrict__ Wq, const float* __restrict__ bq,
    const float* __restrict__ Wk, const float* __restrict__ bk,
    const float* __restrict__ Wv, const float* __restrict__ bv)
{
    const float *X, *W, *bias; float* P;
    if (blockIdx.z == 0)      { X = q; W = Wq; bias = bq; P = g_QP; }
    else if (blockIdx.z == 1) { X = k; W = Wk; bias = bk; P = g_KP; }
    else                      { X = v; W = Wv; bias = bv; P = g_VP; }

    __shared__ uint32_t Xs[128][36];   // ld 36 == 4 (mod 32): frag loads conflict-free
    __shared__ uint32_t Ws[64][36];

    const int tid  = threadIdx.x;
    const int lane = tid & 31;
    const int warp = tid >> 5;
    const int gq   = lane >> 2;        // groupID 0..7
    const int tg   = lane & 3;         // threadID_in_group 0..3
    const int wm   = warp & 3;         // 0..3 (m)
    const int wn   = warp >> 2;        // 0..1 (n)
    const int bm   = blockIdx.x * 128;
    const int bn   = blockIdx.y * 64;

    float acc[2][4][4];
    #pragma unroll
    for (int a = 0; a < 2; a++)
        #pragma unroll
        for (int b2 = 0; b2 < 4; b2++)
            #pragma unroll
            for (int c = 0; c < 4; c++) acc[a][b2][c] = 0.f;

    const int lr = tid >> 3;           // 0..31
    const int lc = (tid & 7) << 2;     // 0,4,...,28

    for (int k0 = 0; k0 < E_; k0 += 32) {
        #pragma unroll
        for (int i = 0; i < 4; i++) {
            int r = lr + i*32;
            float4 t = *(const float4*)(X + (size_t)(bm + r)*E_ + k0 + lc);
            Xs[r][lc+0] = f2tf(t.x); Xs[r][lc+1] = f2tf(t.y);
            Xs[r][lc+2] = f2tf(t.z); Xs[r][lc+3] = f2tf(t.w);
        }
        #pragma unroll
        for (int i = 0; i < 2; i++) {
            int r = lr + i*32;
            float4 t = *(const float4*)(W + (size_t)(bn + r)*E_ + k0 + lc);
            Ws[r][lc+0] = f2tf(t.x); Ws[r][lc+1] = f2tf(t.y);
            Ws[r][lc+2] = f2tf(t.z); Ws[r][lc+3] = f2tf(t.w);
        }
        __syncthreads();

        #pragma unroll
        for (int ks = 0; ks < 4; ks++) {
            uint32_t a0[2], a1[2], a2[2], a3[2];
            #pragma unroll
            for (int mt = 0; mt < 2; mt++) {
                int r = wm*32 + mt*16;
                a0[mt] = Xs[r+gq  ][ks*8+tg  ];
                a1[mt] = Xs[r+gq+8][ks*8+tg  ];
                a2[mt] = Xs[r+gq  ][ks*8+tg+4];
                a3[mt] = Xs[r+gq+8][ks*8+tg+4];
            }
            #pragma unroll
            for (int nt = 0; nt < 4; nt++) {
                int nn = wn*32 + nt*8 + gq;
                uint32_t b0 = Ws[nn][ks*8+tg  ];
                uint32_t b1 = Ws[nn][ks*8+tg+4];
                mma8(acc[0][nt], a0[0], a1[0], a2[0], a3[0], b0, b1);
                mma8(acc[1][nt], a0[1], a1[1], a2[1], a3[1], b0, b1);
            }
        }
        __syncthreads();
    }

    #pragma unroll
    for (int nt = 0; nt < 4; nt++) {
        int n = bn + wn*32 + nt*8 + 2*tg;
        float bi0 = bias[n], bi1 = bias[n+1];
        #pragma unroll
        for (int mt = 0; mt < 2; mt++) {
            int r = bm + wm*32 + mt*16 + gq;
            *(float2*)(P + (size_t)r    *E_ + n) = make_float2(acc[mt][nt][0]+bi0, acc[mt][nt][1]+bi1);
            *(float2*)(P + (size_t)(r+8)*E_ + n) = make_float2(acc[mt][nt][2]+bi0, acc[mt][nt][3]+bi1);
        }
    }
}

// ---------------------------------------------------------------------------
// Flash attention per (b,h): Q/K/V head matrices are CONTIGUOUS (2048,64)
// blocks at offset b*S*E + h*256*E (consequence of the reference's reshape).
// Block = one 64-row Q tile of one head. 128 threads = 4 warps, each warp
// owns 16 Q rows. Online softmax, tf32 mma for QK^T and PV.
// smem: Qs/Ps [64][68], Ks [64][68], Vs [64][72]  (pads chosen so the
// fragment lane->bank maps g*4+tg and tg*8+g are conflict-free).
// ---------------------------------------------------------------------------
#define QS_LD 68
#define KS_LD 68
#define VS_LD 72
#define SMEM_ATTN_BYTES ((64*QS_LD + 64*KS_LD + 64*VS_LD) * 4)

__global__ __launch_bounds__(128) void attn_kernel(
    const float* __restrict__ mask, float* __restrict__ out)
{
    extern __shared__ uint32_t sm[];
    uint32_t* Qs = sm;                         // [64][68], reused as P
    uint32_t* Ks = sm + 64*QS_LD;              // [64][68]
    uint32_t* Vs = sm + 64*QS_LD + 64*KS_LD;   // [64][72]

    const int tid  = threadIdx.x;
    const int lane = tid & 31;
    const int warp = tid >> 5;
    const int gq   = lane >> 2;
    const int tg   = lane & 3;
    const int bh   = blockIdx.y;
    const int b    = bh >> 3;
    const int h    = bh & 7;
    const int q0   = blockIdx.x * 64;

    const float* Qg = g_QP + (size_t)b*(S_*E_) + (size_t)h*HBLK + (size_t)q0*DH;
    const float* Kg = g_KP + (size_t)b*(S_*E_) + (size_t)h*HBLK;
    const float* Vg = g_VP + (size_t)b*(S_*E_) + (size_t)h*HBLK;
    float*       Og = out  + (size_t)b*(S_*E_) + (size_t)h*HBLK;

    const bool use_mask = (g_mask_nonzero != 0);
    const float scale = 0.022097086912079608f;   // 1/sqrt(2048)

    // --- stage Q tile (contiguous 64x64) into smem as tf32 ---
    {
        const float4* src = (const float4*)Qg;
        #pragma unroll
        for (int i = 0; i < 8; i++) {
            int idx = tid + i*128;
            float4 t = src[idx];
            int lin = idx << 2;
            int r = lin >> 6, c = lin & 63;
            uint32_t* p = Qs + r*QS_LD + c;
            p[0] = f2tf(t.x); p[1] = f2tf(t.y); p[2] = f2tf(t.z); p[3] = f2tf(t.w);
        }
    }
    __syncthreads();

    // Q fragments for the whole dh=64 (8 k-steps), held in registers
    uint32_t qa[8][4];
    {
        int r = warp*16;
        #pragma unroll
        for (int ks2 = 0; ks2 < 8; ks2++) {
            qa[ks2][0] = Qs[(r+gq  )*QS_LD + ks2*8+tg  ];
            qa[ks2][1] = Qs[(r+gq+8)*QS_LD + ks2*8+tg  ];
            qa[ks2][2] = Qs[(r+gq  )*QS_LD + ks2*8+tg+4];
            qa[ks2][3] = Qs[(r+gq+8)*QS_LD + ks2*8+tg+4];
        }
    }
    // After this, Qs is reused as the (warp-private-rows) P buffer.

    float mrun0 = -1e30f, mrun1 = -1e30f;
    float lrun0 = 0.f,    lrun1 = 0.f;
    float o[8][4];
    #pragma unroll
    for (int nt = 0; nt < 8; nt++)
        #pragma unroll
        for (int c = 0; c < 4; c++) o[nt][c] = 0.f;

    const int row0  = q0 + warp*16 + gq;   // global q row (first of the two)
    const int prow0 = warp*16 + gq;        // local row in P buffer

    #pragma unroll 1
    for (int kt = 0; kt < 32; kt++) {
        // --- load K and V tiles (each a contiguous 64x64 block) ---
        const float4* ksrc = (const float4*)(Kg + (size_t)kt*4096);
        const float4* vsrc = (const float4*)(Vg + (size_t)kt*4096);
        #pragma unroll
        for (int i = 0; i < 8; i++) {
            int idx = tid + i*128;
            float4 t = ksrc[idx];
            float4 u = vsrc[idx];
            int lin = idx << 2;
            int r = lin >> 6, c = lin & 63;
            uint32_t* pk = Ks + r*KS_LD + c;
            pk[0] = f2tf(t.x); pk[1] = f2tf(t.y); pk[2] = f2tf(t.z); pk[3] = f2tf(t.w);
            uint32_t* pv = Vs + r*VS_LD + c;
            pv[0] = f2tf(u.x); pv[1] = f2tf(u.y); pv[2] = f2tf(u.z); pv[3] = f2tf(u.w);
        }
        __syncthreads();

        // --- S = Q K^T  (16 x 64 per warp) ---
        float s[8][4];
        #pragma unroll
        for (int nt = 0; nt < 8; nt++) {
            s[nt][0] = s[nt][1] = s[nt][2] = s[nt][3] = 0.f;
            #pragma unroll
            for (int ks2 = 0; ks2 < 8; ks2++) {
                uint32_t b0 = Ks[(nt*8+gq)*KS_LD + ks2*8+tg  ];
                uint32_t b1 = Ks[(nt*8+gq)*KS_LD + ks2*8+tg+4];
                mma8(s[nt], qa[ks2][0], qa[ks2][1], qa[ks2][2], qa[ks2][3], b0, b1);
            }
        }

        // --- scale (+ mask) ---
        if (use_mask) {
            #pragma unroll
            for (int nt = 0; nt < 8; nt++) {
                int colb = kt*64 + nt*8 + 2*tg;
                float2 m0 = *(const float2*)(mask + (size_t)row0    *S_ + colb);
                float2 m1 = *(const float2*)(mask + (size_t)(row0+8)*S_ + colb);
                s[nt][0] = s[nt][0]*scale + m0.x;
                s[nt][1] = s[nt][1]*scale + m0.y;
                s[nt][2] = s[nt][2]*scale + m1.x;
                s[nt][3] = s[nt][3]*scale + m1.y;
            }
        } else {
            #pragma unroll
            for (int nt = 0; nt < 8; nt++) {
                s[nt][0] *= scale; s[nt][1] *= scale;
                s[nt][2] *= scale; s[nt][3] *= scale;
            }
        }

        // --- online softmax (rows: gq -> {0,1}, gq+8 -> {2,3}) ---
        float mx0 = fmaxf(s[0][0], s[0][1]);
        float mx1 = fmaxf(s[0][2], s[0][3]);
        #pragma unroll
        for (int nt = 1; nt < 8; nt++) {
            mx0 = fmaxf(mx0, fmaxf(s[nt][0], s[nt][1]));
            mx1 = fmaxf(mx1, fmaxf(s[nt][2], s[nt][3]));
        }
        mx0 = fmaxf(mx0, __shfl_xor_sync(0xffffffffu, mx0, 1));
        mx0 = fmaxf(mx0, __shfl_xor_sync(0xffffffffu, mx0, 2));
        mx1 = fmaxf(mx1, __shfl_xor_sync(0xffffffffu, mx1, 1));
        mx1 = fmaxf(mx1, __shfl_xor_sync(0xffffffffu, mx1, 2));

        float mn0 = fmaxf(mrun0, mx0), mn1 = fmaxf(mrun1, mx1);
        float c0 = __expf(mrun0 - mn0), c1 = __expf(mrun1 - mn1);
        mrun0 = mn0; mrun1 = mn1;

        float su0 = 0.f, su1 = 0.f;
        #pragma unroll
        for (int nt = 0; nt < 8; nt++) {
            float p0 = __expf(s[nt][0] - mn0);
            float p1 = __expf(s[nt][1] - mn0);
            float p2 = __expf(s[nt][2] - mn1);
            float p3 = __expf(s[nt][3] - mn1);
            su0 += p0 + p1; su1 += p2 + p3;
            int cc = nt*8 + 2*tg;
            Qs[ prow0   *QS_LD + cc    ] = f2tf(p0);
            Qs[ prow0   *QS_LD + cc + 1] = f2tf(p1);
            Qs[(prow0+8)*QS_LD + cc    ] = f2tf(p2);
            Qs[(prow0+8)*QS_LD + cc + 1] = f2tf(p3);
        }
        su0 += __shfl_xor_sync(0xffffffffu, su0, 1);
        su0 += __shfl_xor_sync(0xffffffffu, su0, 2);
        su1 += __shfl_xor_sync(0xffffffffu, su1, 1);
        su1 += __shfl_xor_sync(0xffffffffu, su1, 2);
        lrun0 = lrun0*c0 + su0;
        lrun1 = lrun1*c1 + su1;

        #pragma unroll
        for (int nt = 0; nt < 8; nt++) {
            o[nt][0] *= c0; o[nt][1] *= c0;
            o[nt][2] *= c1; o[nt][3] *= c1;
        }
        __syncwarp();   // P rows are warp-private; order STS before LDS

        // --- O += P @ V ---
        #pragma unroll
        for (int ks2 = 0; ks2 < 8; ks2++) {
            uint32_t a0 = Qs[(warp*16+gq  )*QS_LD + ks2*8+tg  ];
            uint32_t a1 = Qs[(warp*16+gq+8)*QS_LD + ks2*8+tg  ];
            uint32_t a2 = Qs[(warp*16+gq  )*QS_LD + ks2*8+tg+4];
            uint32_t a3 = Qs[(warp*16+gq+8)*QS_LD + ks2*8+tg+4];
            #pragma unroll
            for (int nt = 0; nt < 8; nt++) {
                uint32_t b0 = Vs[(ks2*8+tg  )*VS_LD + nt*8+gq];
                uint32_t b1 = Vs[(ks2*8+tg+4)*VS_LD + nt*8+gq];
                mma8(o[nt], a0, a1, a2, a3, b0, b1);
            }
        }
        __syncthreads();   // protect Ks/Vs before next tile's load
    }

    // --- epilogue: normalize and store (head block is contiguous (2048,64)) ---
    float i0 = 1.f/lrun0, i1 = 1.f/lrun1;
    #pragma unroll
    for (int nt = 0; nt < 8; nt++) {
        int cc = nt*8 + 2*tg;
        *(float2*)(Og + (size_t)row0    *DH + cc) = make_float2(o[nt][0]*i0, o[nt][1]*i0);
        *(float2*)(Og + (size_t)(row0+8)*DH + cc) = make_float2(o[nt][2]*i1, o[nt][3]*i1);
    }
}

// ---------------------------------------------------------------------------
extern "C" void kernel_launch(void* const* d_in, const int* in_sizes, int n_in,
                              void* d_out, int out_size)
{
    const float* q    = (const float*)d_in[0];
    const float* k    = (const float*)d_in[1];
    const float* v    = (const float*)d_in[2];
    const float* mask = (const float*)d_in[3];
    const float* Wq   = (const float*)d_in[4];
    const float* bq   = (const float*)d_in[5];
    const float* Wk   = (const float*)d_in[6];
    const float* bk   = (const float*)d_in[7];
    const float* Wv   = (const float*)d_in[8];
    const float* bv   = (const float*)d_in[9];
    float* out = (float*)d_out;

    (void)in_sizes; (void)n_in; (void)out_size;

    cudaFuncSetAttribute(attn_kernel,
                         cudaFuncAttributeMaxDynamicSharedMemorySize,
                         SMEM_ATTN_BYTES);

    clear_flag_kernel<<<1, 1>>>();
    scan_mask_kernel<<<128, 256>>>(mask);
    proj_kernel<<<dim3(32, 8, 3), 256>>>(q, k, v, Wq, bq, Wk, bk, Wv, bv);
    attn_kernel<<<dim3(32, 16), 128, SMEM_ATTN_BYTES>>>(mask, out);
}

// round 3
// speedup vs baseline: 1.1561x; 1.1561x over previous
#include <cuda_runtime.h>
#include <cuda_bf16.h>
#include <cstdint>
#include <cstddef>

// Problem dims (fixed by setup_inputs)
#define B_  2
#define S_  2048
#define E_  512
#define HN  8
#define DH  64          // E_/HN
#define HBLK (256*E_)   // elements per head block inside the (S,E) projection

// Scratch (no cudaMalloc allowed) — 3 x 8MB fp32
__device__ float g_QP[B_*S_*E_];
__device__ float g_KP[B_*S_*E_];
__device__ float g_VP[B_*S_*E_];
__device__ int   g_mask_nonzero;

__device__ __forceinline__ uint32_t f2tf(float f) {
    uint32_t u;
    asm("cvt.rna.tf32.f32 %0, %1;" : "=r"(u) : "f"(f));
    return u;
}

__device__ __forceinline__ void mma8(float (&c)[4],
    uint32_t a0, uint32_t a1, uint32_t a2, uint32_t a3,
    uint32_t b0, uint32_t b1)
{
    asm volatile(
        "mma.sync.aligned.m16n8k8.row.col.f32.tf32.tf32.f32 "
        "{%0,%1,%2,%3}, {%4,%5,%6,%7}, {%8,%9}, {%0,%1,%2,%3};\n"
        : "+f"(c[0]), "+f"(c[1]), "+f"(c[2]), "+f"(c[3])
        : "r"(a0), "r"(a1), "r"(a2), "r"(a3), "r"(b0), "r"(b1));
}

// bf16 m16n8k16 mma, fp32 accumulate
__device__ __forceinline__ void mmabf(float* c, const uint32_t* a, uint32_t b0, uint32_t b1)
{
    asm volatile(
        "mma.sync.aligned.m16n8k16.row.col.f32.bf16.bf16.f32 "
        "{%0,%1,%2,%3}, {%4,%5,%6,%7}, {%8,%9}, {%0,%1,%2,%3};\n"
        : "+f"(c[0]), "+f"(c[1]), "+f"(c[2]), "+f"(c[3])
        : "r"(a[0]), "r"(a[1]), "r"(a[2]), "r"(a[3]), "r"(b0), "r"(b1));
}

__device__ __forceinline__ uint32_t cvta_s(const void* p) {
    return (uint32_t)__cvta_generic_to_shared(p);
}

__device__ __forceinline__ void ldsm4(uint32_t& r0, uint32_t& r1, uint32_t& r2, uint32_t& r3, uint32_t a) {
    asm volatile("ldmatrix.sync.aligned.m8n8.x4.shared.b16 {%0,%1,%2,%3}, [%4];"
        : "=r"(r0), "=r"(r1), "=r"(r2), "=r"(r3) : "r"(a));
}
__device__ __forceinline__ void ldsm4t(uint32_t& r0, uint32_t& r1, uint32_t& r2, uint32_t& r3, uint32_t a) {
    asm volatile("ldmatrix.sync.aligned.m8n8.x4.trans.shared.b16 {%0,%1,%2,%3}, [%4];"
        : "=r"(r0), "=r"(r1), "=r"(r2), "=r"(r3) : "r"(a));
}

// pack two floats -> bf16x2 (lo = a, hi = b)
__device__ __forceinline__ uint32_t pk2(float a, float b) {
    __nv_bfloat162 t = __floats2bfloat162_rn(a, b);
    return *(uint32_t*)&t;
}
// hi/lo split of a float pair into two bf16x2
__device__ __forceinline__ void hilo(float a, float b, uint32_t& hi, uint32_t& lo) {
    __nv_bfloat162 h = __floats2bfloat162_rn(a, b);
    hi = *(uint32_t*)&h;
    float ra = a - __bfloat162float(h.x);
    float rb = b - __bfloat162float(h.y);
    __nv_bfloat162 l2 = __floats2bfloat162_rn(ra, rb);
    lo = *(uint32_t*)&l2;
}

// ---------------------------------------------------------------------------
// Mask scan
// ---------------------------------------------------------------------------
__global__ void clear_flag_kernel() { g_mask_nonzero = 0; }

__global__ void scan_mask_kernel(const float* __restrict__ mask) {
    int stride = gridDim.x * blockDim.x;
    int i = blockIdx.x * blockDim.x + threadIdx.x;
    const int n4 = (S_*S_) >> 2;
    const float4* m4 = (const float4*)mask;
    int f = 0;
    for (; i < n4; i += stride) {
        float4 t = m4[i];
        if (t.x != 0.f || t.y != 0.f || t.z != 0.f || t.w != 0.f) f = 1;
    }
    if (f) g_mask_nonzero = 1;
}

// ---------------------------------------------------------------------------
// Projection GEMM (tf32):  P = X W^T + b
// ---------------------------------------------------------------------------
__global__ __launch_bounds__(256) void proj_kernel(
    const float* __restrict__ q, const float* __restrict__ k, const float* __restrict__ v,
    const float* __restrict__ Wq, const float* __restrict__ bq,
    const float* __restrict__ Wk, const float* __restrict__ bk,
    const float* __restrict__ Wv, const float* __restrict__ bv)
{
    const float *X, *W, *bias; float* P;
    if (blockIdx.z == 0)      { X = q; W = Wq; bias = bq; P = g_QP; }
    else if (blockIdx.z == 1) { X = k; W = Wk; bias = bk; P = g_KP; }
    else                      { X = v; W = Wv; bias = bv; P = g_VP; }

    __shared__ uint32_t Xs[128][36];
    __shared__ uint32_t Ws[64][36];

    const int tid  = threadIdx.x;
    const int lane = tid & 31;
    const int warp = tid >> 5;
    const int gq   = lane >> 2;
    const int tg   = lane & 3;
    const int wm   = warp & 3;
    const int wn   = warp >> 2;
    const int bm   = blockIdx.x * 128;
    const int bn   = blockIdx.y * 64;

    float acc[2][4][4];
    #pragma unroll
    for (int a = 0; a < 2; a++)
        #pragma unroll
        for (int b2 = 0; b2 < 4; b2++)
            #pragma unroll
            for (int c = 0; c < 4; c++) acc[a][b2][c] = 0.f;

    const int lr = tid >> 3;
    const int lc = (tid & 7) << 2;

    for (int k0 = 0; k0 < E_; k0 += 32) {
        #pragma unroll
        for (int i = 0; i < 4; i++) {
            int r = lr + i*32;
            float4 t = *(const float4*)(X + (size_t)(bm + r)*E_ + k0 + lc);
            Xs[r][lc+0] = f2tf(t.x); Xs[r][lc+1] = f2tf(t.y);
            Xs[r][lc+2] = f2tf(t.z); Xs[r][lc+3] = f2tf(t.w);
        }
        #pragma unroll
        for (int i = 0; i < 2; i++) {
            int r = lr + i*32;
            float4 t = *(const float4*)(W + (size_t)(bn + r)*E_ + k0 + lc);
            Ws[r][lc+0] = f2tf(t.x); Ws[r][lc+1] = f2tf(t.y);
            Ws[r][lc+2] = f2tf(t.z); Ws[r][lc+3] = f2tf(t.w);
        }
        __syncthreads();

        #pragma unroll
        for (int ks = 0; ks < 4; ks++) {
            uint32_t a0[2], a1[2], a2[2], a3[2];
            #pragma unroll
            for (int mt = 0; mt < 2; mt++) {
                int r = wm*32 + mt*16;
                a0[mt] = Xs[r+gq  ][ks*8+tg  ];
                a1[mt] = Xs[r+gq+8][ks*8+tg  ];
                a2[mt] = Xs[r+gq  ][ks*8+tg+4];
                a3[mt] = Xs[r+gq+8][ks*8+tg+4];
            }
            #pragma unroll
            for (int nt = 0; nt < 4; nt++) {
                int nn = wn*32 + nt*8 + gq;
                uint32_t b0 = Ws[nn][ks*8+tg  ];
                uint32_t b1 = Ws[nn][ks*8+tg+4];
                mma8(acc[0][nt], a0[0], a1[0], a2[0], a3[0], b0, b1);
                mma8(acc[1][nt], a0[1], a1[1], a2[1], a3[1], b0, b1);
            }
        }
        __syncthreads();
    }

    #pragma unroll
    for (int nt = 0; nt < 4; nt++) {
        int n = bn + wn*32 + nt*8 + 2*tg;
        float bi0 = bias[n], bi1 = bias[n+1];
        #pragma unroll
        for (int mt = 0; mt < 2; mt++) {
            int r = bm + wm*32 + mt*16 + gq;
            *(float2*)(P + (size_t)r    *E_ + n) = make_float2(acc[mt][nt][0]+bi0, acc[mt][nt][1]+bi1);
            *(float2*)(P + (size_t)(r+8)*E_ + n) = make_float2(acc[mt][nt][2]+bi0, acc[mt][nt][3]+bi1);
        }
    }
}

// ---------------------------------------------------------------------------
// Flash attention, bf16 tensor-core version.
// Block: 128 threads (4 warps), Q tile 128 rows (warp owns 32 rows = 2 m16).
// QK^T: plain bf16 + ldmatrix. PV: bf16 hi/lo split (3 mma terms), P stays
// in registers (C-frag of QK == A-frag of PV). Double-buffered K/V smem,
// one __syncthreads per tile; LDG prefetch hidden behind QK mma.
// Rows padded to 144B so every ldmatrix phase is bank-conflict-free.
// ---------------------------------------------------------------------------
#define LDB 72
#define ROWB 144
#define TILE_BYTES (64*ROWB)        // 9216
#define BUF_BYTES  (3*TILE_BYTES)   // K, Vhi, Vlo
#define SMEM_ATTN  (2*BUF_BYTES)    // 55296

__global__ __launch_bounds__(128) void attn_kernel(
    const float* __restrict__ mask, float* __restrict__ out)
{
    extern __shared__ __align__(16) char smem[];

    const int tid  = threadIdx.x;
    const int lane = tid & 31;
    const int warp = tid >> 5;
    const int gq   = lane >> 2;
    const int tg   = lane & 3;
    const int bh   = blockIdx.y;
    const int b    = bh >> 3;
    const int h    = bh & 7;
    const int q0   = blockIdx.x * 128;

    const float* Qg = g_QP + (size_t)b*(S_*E_) + (size_t)h*HBLK + (size_t)q0*DH;
    const float* Kg = g_KP + (size_t)b*(S_*E_) + (size_t)h*HBLK;
    const float* Vg = g_VP + (size_t)b*(S_*E_) + (size_t)h*HBLK;
    float*       Og = out  + (size_t)b*(S_*E_) + (size_t)h*HBLK;

    const bool use_mask = (g_mask_nonzero != 0);
    const float scale = 0.022097086912079608f;   // 1/sqrt(2048)

    // ---- stage Q (128x64) as bf16 into the front of the buffer area ----
    {
        const float4* src = (const float4*)Qg;
        #pragma unroll
        for (int i = 0; i < 16; i++) {
            int idx = tid + i*128;
            float4 t = src[idx];
            int r = idx >> 4, c = (idx & 15) << 2;
            *(uint2*)(smem + r*ROWB + c*2) = make_uint2(pk2(t.x, t.y), pk2(t.z, t.w));
        }
    }
    __syncthreads();

    // Q A-fragments (2 m-tiles x 4 k16-steps), bf16, held in registers
    uint32_t qa[2][4][4];
    {
        uint32_t qbase = cvta_s(smem) + (uint32_t)((warp*32 + (lane & 15))*ROWB + (lane >> 4)*16);
        #pragma unroll
        for (int mt = 0; mt < 2; mt++)
            #pragma unroll
            for (int ks = 0; ks < 4; ks++)
                ldsm4(qa[mt][ks][0], qa[mt][ks][1], qa[mt][ks][2], qa[mt][ks][3],
                      qbase + (uint32_t)(mt*16*ROWB + ks*32));
    }
    __syncthreads();

    // ---- stage K/V tile 0 into buffer 0 ----
    {
        const float4* ksrc = (const float4*)Kg;
        const float4* vsrc = (const float4*)Vg;
        #pragma unroll
        for (int i = 0; i < 8; i++) {
            int idx = tid + i*128;
            int r = idx >> 4, c = (idx & 15) << 2;
            float4 t = ksrc[idx];
            *(uint2*)(smem + r*ROWB + c*2) = make_uint2(pk2(t.x, t.y), pk2(t.z, t.w));
            float4 u = vsrc[idx];
            uint32_t h0, l0, h1, l1;
            hilo(u.x, u.y, h0, l0);
            hilo(u.z, u.w, h1, l1);
            *(uint2*)(smem + TILE_BYTES   + r*ROWB + c*2) = make_uint2(h0, h1);
            *(uint2*)(smem + 2*TILE_BYTES + r*ROWB + c*2) = make_uint2(l0, l1);
        }
    }

    const uint32_t sbase  = cvta_s(smem);
    const uint32_t k_lane = (uint32_t)((((lane & 7) + ((lane >> 4) & 1)*8))*ROWB + ((lane >> 3) & 1)*16);
    const uint32_t v_lane = (uint32_t)((((lane & 7) + ((lane >> 3) & 1)*8))*ROWB + ((lane >> 4) & 1)*16);

    float o[2][8][4];
    #pragma unroll
    for (int mt = 0; mt < 2; mt++)
        #pragma unroll
        for (int nt = 0; nt < 8; nt++)
            #pragma unroll
            for (int c = 0; c < 4; c++) o[mt][nt][c] = 0.f;

    float mrun[2][2] = {{-1e30f, -1e30f}, {-1e30f, -1e30f}};
    float lrun[2][2] = {{0.f, 0.f}, {0.f, 0.f}};

    #pragma unroll 1
    for (int kt = 0; kt < 32; kt++) {
        __syncthreads();                       // buf[p] ready for all warps
        const int p = kt & 1;
        const uint32_t bufb = sbase + (uint32_t)(p*BUF_BYTES);
        char* nb = smem + (1 - p)*BUF_BYTES;   // staging target for tile kt+1

        // prefetch K(kt+1) into registers (latency hidden behind QK mma)
        float4 kreg[8];
        if (kt < 31) {
            const float4* ksrc = (const float4*)(Kg + (size_t)(kt + 1)*4096);
            #pragma unroll
            for (int i = 0; i < 8; i++) kreg[i] = ksrc[tid + i*128];
        }

        // ---- S = Q K^T : bf16 m16n8k16 ----
        float s[2][8][4];
        #pragma unroll
        for (int mt = 0; mt < 2; mt++)
            #pragma unroll
            for (int nt = 0; nt < 8; nt++)
                #pragma unroll
                for (int c = 0; c < 4; c++) s[mt][nt][c] = 0.f;

        #pragma unroll
        for (int ks = 0; ks < 4; ks++) {
            #pragma unroll
            for (int np = 0; np < 4; np++) {
                uint32_t a = bufb + k_lane + (uint32_t)(np*16*ROWB + ks*32);
                uint32_t b0, b1, b2, b3;
                ldsm4(b0, b1, b2, b3, a);
                mmabf(s[0][np*2  ], qa[0][ks], b0, b1);
                mmabf(s[0][np*2+1], qa[0][ks], b2, b3);
                mmabf(s[1][np*2  ], qa[1][ks], b0, b1);
                mmabf(s[1][np*2+1], qa[1][ks], b2, b3);
            }
        }

        // store K(kt+1) as bf16
        if (kt < 31) {
            #pragma unroll
            for (int i = 0; i < 8; i++) {
                int idx = tid + i*128;
                int r = idx >> 4, c = (idx & 15) << 2;
                *(uint2*)(nb + r*ROWB + c*2) =
                    make_uint2(pk2(kreg[i].x, kreg[i].y), pk2(kreg[i].z, kreg[i].w));
            }
        }

        // prefetch V(kt+1)
        float4 vreg[8];
        if (kt < 31) {
            const float4* vsrc = (const float4*)(Vg + (size_t)(kt + 1)*4096);
            #pragma unroll
            for (int i = 0; i < 8; i++) vreg[i] = vsrc[tid + i*128];
        }

        // ---- scale (+ mask), online softmax ----
        #pragma unroll
        for (int mt = 0; mt < 2; mt++) {
            if (use_mask) {
                int row0 = q0 + warp*32 + mt*16 + gq;
                #pragma unroll
                for (int nt = 0; nt < 8; nt++) {
                    int colb = kt*64 + nt*8 + 2*tg;
                    float2 m0 = *(const float2*)(mask + (size_t)row0     *S_ + colb);
                    float2 m1 = *(const float2*)(mask + (size_t)(row0+8) *S_ + colb);
                    s[mt][nt][0] = s[mt][nt][0]*scale + m0.x;
                    s[mt][nt][1] = s[mt][nt][1]*scale + m0.y;
                    s[mt][nt][2] = s[mt][nt][2]*scale + m1.x;
                    s[mt][nt][3] = s[mt][nt][3]*scale + m1.y;
                }
            } else {
                #pragma unroll
                for (int nt = 0; nt < 8; nt++) {
                    s[mt][nt][0] *= scale; s[mt][nt][1] *= scale;
                    s[mt][nt][2] *= scale; s[mt][nt][3] *= scale;
                }
            }

            float mx0 = fmaxf(s[mt][0][0], s[mt][0][1]);
            float mx1 = fmaxf(s[mt][0][2], s[mt][0][3]);
            #pragma unroll
            for (int nt = 1; nt < 8; nt++) {
                mx0 = fmaxf(mx0, fmaxf(s[mt][nt][0], s[mt][nt][1]));
                mx1 = fmaxf(mx1, fmaxf(s[mt][nt][2], s[mt][nt][3]));
            }
            mx0 = fmaxf(mx0, __shfl_xor_sync(0xffffffffu, mx0, 1));
            mx0 = fmaxf(mx0, __shfl_xor_sync(0xffffffffu, mx0, 2));
            mx1 = fmaxf(mx1, __shfl_xor_sync(0xffffffffu, mx1, 1));
            mx1 = fmaxf(mx1, __shfl_xor_sync(0xffffffffu, mx1, 2));

            float mn0 = fmaxf(mrun[mt][0], mx0), mn1 = fmaxf(mrun[mt][1], mx1);
            float c0 = __expf(mrun[mt][0] - mn0), c1 = __expf(mrun[mt][1] - mn1);
            mrun[mt][0] = mn0; mrun[mt][1] = mn1;

            float su0 = 0.f, su1 = 0.f;
            #pragma unroll
            for (int nt = 0; nt < 8; nt++) {
                float p0 = __expf(s[mt][nt][0] - mn0);
                float p1 = __expf(s[mt][nt][1] - mn0);
                float p2 = __expf(s[mt][nt][2] - mn1);
                float p3 = __expf(s[mt][nt][3] - mn1);
                su0 += p0 + p1; su1 += p2 + p3;
                s[mt][nt][0] = p0; s[mt][nt][1] = p1;
                s[mt][nt][2] = p2; s[mt][nt][3] = p3;
            }
            su0 += __shfl_xor_sync(0xffffffffu, su0, 1);
            su0 += __shfl_xor_sync(0xffffffffu, su0, 2);
            su1 += __shfl_xor_sync(0xffffffffu, su1, 1);
            su1 += __shfl_xor_sync(0xffffffffu, su1, 2);
            lrun[mt][0] = lrun[mt][0]*c0 + su0;
            lrun[mt][1] = lrun[mt][1]*c1 + su1;

            #pragma unroll
            for (int nt = 0; nt < 8; nt++) {
                o[mt][nt][0] *= c0; o[mt][nt][1] *= c0;
                o[mt][nt][2] *= c1; o[mt][nt][3] *= c1;
            }
        }

        // ---- pack P into bf16 hi/lo A-fragments (register-only) ----
        uint32_t ah[2][4][4], al[2][4][4];
        #pragma unroll
        for (int mt = 0; mt < 2; mt++) {
            #pragma unroll
            for (int ks = 0; ks < 4; ks++) {
                hilo(s[mt][2*ks  ][0], s[mt][2*ks  ][1], ah[mt][ks][0], al[mt][ks][0]);
                hilo(s[mt][2*ks  ][2], s[mt][2*ks  ][3], ah[mt][ks][1], al[mt][ks][1]);
                hilo(s[mt][2*ks+1][0], s[mt][2*ks+1][1], ah[mt][ks][2], al[mt][ks][2]);
                hilo(s[mt][2*ks+1][2], s[mt][2*ks+1][3], ah[mt][ks][3], al[mt][ks][3]);
            }
        }

        // store V(kt+1) hi/lo
        if (kt < 31) {
            #pragma unroll
            for (int i = 0; i < 8; i++) {
                int idx = tid + i*128;
                int r = idx >> 4, c = (idx & 15) << 2;
                uint32_t h0, l0, h1, l1;
                hilo(vreg[i].x, vreg[i].y, h0, l0);
                hilo(vreg[i].z, vreg[i].w, h1, l1);
                *(uint2*)(nb + TILE_BYTES   + r*ROWB + c*2) = make_uint2(h0, h1);
                *(uint2*)(nb + 2*TILE_BYTES + r*ROWB + c*2) = make_uint2(l0, l1);
            }
        }

        // ---- O += P @ V  (hi*hi + lo*hi + hi*lo) ----
        #pragma unroll
        for (int ks = 0; ks < 4; ks++) {
            #pragma unroll
            for (int np = 0; np < 4; np++) {
                uint32_t va = bufb + (uint32_t)TILE_BYTES + v_lane
                            + (uint32_t)(ks*16*ROWB + np*32);
                uint32_t h0, h1, h2, h3, l0, l1, l2, l3;
                ldsm4t(h0, h1, h2, h3, va);
                ldsm4t(l0, l1, l2, l3, va + (uint32_t)TILE_BYTES);
                #pragma unroll
                for (int mt = 0; mt < 2; mt++) {
                    mmabf(o[mt][np*2  ], ah[mt][ks], h0, h1);
                    mmabf(o[mt][np*2  ], al[mt][ks], h0, h1);
                    mmabf(o[mt][np*2  ], ah[mt][ks], l0, l1);
                    mmabf(o[mt][np*2+1], ah[mt][ks], h2, h3);
                    mmabf(o[mt][np*2+1], al[mt][ks], h2, h3);
                    mmabf(o[mt][np*2+1], ah[mt][ks], l2, l3);
                }
            }
        }
    }

    // ---- epilogue ----
    #pragma unroll
    for (int mt = 0; mt < 2; mt++) {
        float i0 = 1.f / lrun[mt][0], i1 = 1.f / lrun[mt][1];
        int r0 = q0 + warp*32 + mt*16 + gq;
        #pragma unroll
        for (int nt = 0; nt < 8; nt++) {
            int cc = nt*8 + 2*tg;
            *(float2*)(Og + (size_t)r0    *DH + cc) = make_float2(o[mt][nt][0]*i0, o[mt][nt][1]*i0);
            *(float2*)(Og + (size_t)(r0+8)*DH + cc) = make_float2(o[mt][nt][2]*i1, o[mt][nt][3]*i1);
        }
    }
}

// ---------------------------------------------------------------------------
extern "C" void kernel_launch(void* const* d_in, const int* in_sizes, int n_in,
                              void* d_out, int out_size)
{
    const float* q    = (const float*)d_in[0];
    const float* k    = (const float*)d_in[1];
    const float* v    = (const float*)d_in[2];
    const float* mask = (const float*)d_in[3];
    const float* Wq   = (const float*)d_in[4];
    const float* bq   = (const float*)d_in[5];
    const float* Wk   = (const float*)d_in[6];
    const float* bk   = (const float*)d_in[7];
    const float* Wv   = (const float*)d_in[8];
    const float* bv   = (const float*)d_in[9];
    float* out = (float*)d_out;

    (void)in_sizes; (void)n_in; (void)out_size;

    cudaFuncSetAttribute(attn_kernel,
                         cudaFuncAttributeMaxDynamicSharedMemorySize,
                         SMEM_ATTN);

    clear_flag_kernel<<<1, 1>>>();
    scan_mask_kernel<<<128, 256>>>(mask);
    proj_kernel<<<dim3(32, 8, 3), 256>>>(q, k, v, Wq, bq, Wk, bk, Wv, bv);
    attn_kernel<<<dim3(16, 16), 128, SMEM_ATTN>>>(mask, out);
}

// round 5
// speedup vs baseline: 1.8255x; 1.5791x over previous
#include <cuda_runtime.h>
#include <cuda_fp16.h>
#include <cstdint>
#include <cstddef>

// Problem dims (fixed by setup_inputs)
#define B_  2
#define S_  2048
#define E_  512
#define HN  8
#define DH  64
#define HBLK (256*E_)

// fp16 projection outputs (attention is the only consumer)
__device__ __half g_QP[B_*S_*E_];
__device__ __half g_KP[B_*S_*E_];
__device__ __half g_VP[B_*S_*E_];
__device__ int    g_mask_nonzero;

__device__ __forceinline__ uint32_t f2tf(float f) {
    uint32_t u;
    asm("cvt.rna.tf32.f32 %0, %1;" : "=r"(u) : "f"(f));
    return u;
}

__device__ __forceinline__ void mma8(float (&c)[4],
    uint32_t a0, uint32_t a1, uint32_t a2, uint32_t a3,
    uint32_t b0, uint32_t b1)
{
    asm volatile(
        "mma.sync.aligned.m16n8k8.row.col.f32.tf32.tf32.f32 "
        "{%0,%1,%2,%3}, {%4,%5,%6,%7}, {%8,%9}, {%0,%1,%2,%3};\n"
        : "+f"(c[0]), "+f"(c[1]), "+f"(c[2]), "+f"(c[3])
        : "r"(a0), "r"(a1), "r"(a2), "r"(a3), "r"(b0), "r"(b1));
}

// fp16 m16n8k16 mma, fp32 accumulate
__device__ __forceinline__ void mmah(float* c, const uint32_t* a, uint32_t b0, uint32_t b1)
{
    asm volatile(
        "mma.sync.aligned.m16n8k16.row.col.f32.f16.f16.f32 "
        "{%0,%1,%2,%3}, {%4,%5,%6,%7}, {%8,%9}, {%0,%1,%2,%3};\n"
        : "+f"(c[0]), "+f"(c[1]), "+f"(c[2]), "+f"(c[3])
        : "r"(a[0]), "r"(a[1]), "r"(a[2]), "r"(a[3]), "r"(b0), "r"(b1));
}

__device__ __forceinline__ uint32_t cvta_s(const void* p) {
    return (uint32_t)__cvta_generic_to_shared(p);
}

__device__ __forceinline__ void ldsm4(uint32_t& r0, uint32_t& r1, uint32_t& r2, uint32_t& r3, uint32_t a) {
    asm volatile("ldmatrix.sync.aligned.m8n8.x4.shared.b16 {%0,%1,%2,%3}, [%4];"
        : "=r"(r0), "=r"(r1), "=r"(r2), "=r"(r3) : "r"(a));
}
__device__ __forceinline__ void ldsm4t(uint32_t& r0, uint32_t& r1, uint32_t& r2, uint32_t& r3, uint32_t a) {
    asm volatile("ldmatrix.sync.aligned.m8n8.x4.trans.shared.b16 {%0,%1,%2,%3}, [%4];"
        : "=r"(r0), "=r"(r1), "=r"(r2), "=r"(r3) : "r"(a));
}

__device__ __forceinline__ uint32_t pk2h(float a, float b) {
    __half2 t = __floats2half2_rn(a, b);
    return *(uint32_t*)&t;
}

__device__ __forceinline__ void cpasync16(uint32_t dst, const void* src) {
    asm volatile("cp.async.cg.shared.global [%0], [%1], 16;" :: "r"(dst), "l"(src));
}
__device__ __forceinline__ void cp_commit() {
    asm volatile("cp.async.commit_group;");
}
__device__ __forceinline__ void cp_wait0() {
    asm volatile("cp.async.wait_group 0;");
}

// ---------------------------------------------------------------------------
// Mask scan
// ---------------------------------------------------------------------------
__global__ void clear_flag_kernel() { g_mask_nonzero = 0; }

__global__ void scan_mask_kernel(const float* __restrict__ mask) {
    int stride = gridDim.x * blockDim.x;
    int i = blockIdx.x * blockDim.x + threadIdx.x;
    const int n4 = (S_*S_) >> 2;
    const float4* m4 = (const float4*)mask;
    int f = 0;
    for (; i < n4; i += stride) {
        float4 t = m4[i];
        if (t.x != 0.f || t.y != 0.f || t.z != 0.f || t.w != 0.f) f = 1;
    }
    if (f) g_mask_nonzero = 1;
}

// ---------------------------------------------------------------------------
// Projection GEMM (tf32 compute, fp16 output):  P = f16(X W^T + b)
// ---------------------------------------------------------------------------
__global__ __launch_bounds__(256) void proj_kernel(
    const float* __restrict__ q, const float* __restrict__ k, const float* __restrict__ v,
    const float* __restrict__ Wq, const float* __restrict__ bq,
    const float* __restrict__ Wk, const float* __restrict__ bk,
    const float* __restrict__ Wv, const float* __restrict__ bv)
{
    const float *X, *W, *bias; __half* P;
    if (blockIdx.z == 0)      { X = q; W = Wq; bias = bq; P = g_QP; }
    else if (blockIdx.z == 1) { X = k; W = Wk; bias = bk; P = g_KP; }
    else                      { X = v; W = Wv; bias = bv; P = g_VP; }

    __shared__ uint32_t Xs[128][36];
    __shared__ uint32_t Ws[64][36];

    const int tid  = threadIdx.x;
    const int lane = tid & 31;
    const int warp = tid >> 5;
    const int gq   = lane >> 2;
    const int tg   = lane & 3;
    const int wm   = warp & 3;
    const int wn   = warp >> 2;
    const int bm   = blockIdx.x * 128;
    const int bn   = blockIdx.y * 64;

    float acc[2][4][4];
    #pragma unroll
    for (int a = 0; a < 2; a++)
        #pragma unroll
        for (int b2 = 0; b2 < 4; b2++)
            #pragma unroll
            for (int c = 0; c < 4; c++) acc[a][b2][c] = 0.f;

    const int lr = tid >> 3;
    const int lc = (tid & 7) << 2;

    for (int k0 = 0; k0 < E_; k0 += 32) {
        #pragma unroll
        for (int i = 0; i < 4; i++) {
            int r = lr + i*32;
            float4 t = *(const float4*)(X + (size_t)(bm + r)*E_ + k0 + lc);
            Xs[r][lc+0] = f2tf(t.x); Xs[r][lc+1] = f2tf(t.y);
            Xs[r][lc+2] = f2tf(t.z); Xs[r][lc+3] = f2tf(t.w);
        }
        #pragma unroll
        for (int i = 0; i < 2; i++) {
            int r = lr + i*32;
            float4 t = *(const float4*)(W + (size_t)(bn + r)*E_ + k0 + lc);
            Ws[r][lc+0] = f2tf(t.x); Ws[r][lc+1] = f2tf(t.y);
            Ws[r][lc+2] = f2tf(t.z); Ws[r][lc+3] = f2tf(t.w);
        }
        __syncthreads();

        #pragma unroll
        for (int ks = 0; ks < 4; ks++) {
            uint32_t a0[2], a1[2], a2[2], a3[2];
            #pragma unroll
            for (int mt = 0; mt < 2; mt++) {
                int r = wm*32 + mt*16;
                a0[mt] = Xs[r+gq  ][ks*8+tg  ];
                a1[mt] = Xs[r+gq+8][ks*8+tg  ];
                a2[mt] = Xs[r+gq  ][ks*8+tg+4];
                a3[mt] = Xs[r+gq+8][ks*8+tg+4];
            }
            #pragma unroll
            for (int nt = 0; nt < 4; nt++) {
                int nn = wn*32 + nt*8 + gq;
                uint32_t b0 = Ws[nn][ks*8+tg  ];
                uint32_t b1 = Ws[nn][ks*8+tg+4];
                mma8(acc[0][nt], a0[0], a1[0], a2[0], a3[0], b0, b1);
                mma8(acc[1][nt], a0[1], a1[1], a2[1], a3[1], b0, b1);
            }
        }
        __syncthreads();
    }

    #pragma unroll
    for (int nt = 0; nt < 4; nt++) {
        int n = bn + wn*32 + nt*8 + 2*tg;
        float bi0 = bias[n], bi1 = bias[n+1];
        #pragma unroll
        for (int mt = 0; mt < 2; mt++) {
            int r = bm + wm*32 + mt*16 + gq;
            *(__half2*)(P + (size_t)r    *E_ + n) = __floats2half2_rn(acc[mt][nt][0]+bi0, acc[mt][nt][1]+bi1);
            *(__half2*)(P + (size_t)(r+8)*E_ + n) = __floats2half2_rn(acc[mt][nt][2]+bi0, acc[mt][nt][3]+bi1);
        }
    }
}

// ---------------------------------------------------------------------------
// Flash attention, fp16 tensor-core version.
// Block: 128 threads (4 warps), Q tile 128 rows (warp owns 32 rows = 2 m16).
// QK^T + PV both fp16 m16n8k16 with fp32 accumulate; P register-resident.
// K/V tiles double-buffered in smem, filled by cp.async (overlapped with
// compute). Rows padded to 144B so every ldmatrix phase is conflict-free.
// ---------------------------------------------------------------------------
#define ROWB 144
#define QBUF_BYTES (128*ROWB)      // 18432
#define TILE_BYTES (64*ROWB)       // 9216
#define BUF_BYTES  (2*TILE_BYTES)  // K + V per stage
#define SMEM_ATTN  (QBUF_BYTES + 2*BUF_BYTES)   // 55296

__global__ __launch_bounds__(128) void attn_kernel(
    const float* __restrict__ mask, float* __restrict__ out)
{
    extern __shared__ __align__(16) char smem[];

    const int tid  = threadIdx.x;
    const int lane = tid & 31;
    const int warp = tid >> 5;
    const int gq   = lane >> 2;
    const int tg   = lane & 3;
    const int bh   = blockIdx.y;
    const int b    = bh >> 3;
    const int h    = bh & 7;
    const int q0   = blockIdx.x * 128;

    const __half* Qg = g_QP + (size_t)b*(S_*E_) + (size_t)h*HBLK + (size_t)q0*DH;
    const __half* Kg = g_KP + (size_t)b*(S_*E_) + (size_t)h*HBLK;
    const __half* Vg = g_VP + (size_t)b*(S_*E_) + (size_t)h*HBLK;
    float*        Og = out  + (size_t)b*(S_*E_) + (size_t)h*HBLK;

    const bool use_mask = (g_mask_nonzero != 0);
    const float scale = 0.022097086912079608f;   // 1/sqrt(2048)

    const uint32_t sbase = cvta_s(smem);
    // chunk id for this thread within a 64x64 fp16 tile (512 x 16B chunks)
    // row = idx>>3, col16 = idx&7
    const int trow = tid >> 3;         // for K/V: rows trow, trow+16, +32, +48
    const int tc16 = tid & 7;

    // ---- preload Q (128x64) + K/V tile 0 via cp.async ----
    {
        #pragma unroll
        for (int i = 0; i < 8; i++) {       // Q: 1024 chunks
            int idx = tid + i*128;
            int r = idx >> 3, c = idx & 7;
            cpasync16(sbase + (uint32_t)(r*ROWB + c*16), Qg + r*DH + c*8);
        }
        #pragma unroll
        for (int i = 0; i < 4; i++) {       // K0 + V0: 512 chunks each
            int r = trow + i*16;
            cpasync16(sbase + (uint32_t)(QBUF_BYTES + r*ROWB + tc16*16), Kg + r*DH + tc16*8);
            cpasync16(sbase + (uint32_t)(QBUF_BYTES + TILE_BYTES + r*ROWB + tc16*16), Vg + r*DH + tc16*8);
        }
        cp_commit();
        cp_wait0();
    }
    __syncthreads();

    // Q A-fragments (2 m-tiles x 4 k16-steps), held in registers
    uint32_t qa[2][4][4];
    {
        uint32_t qbase = sbase + (uint32_t)((warp*32 + (lane & 15))*ROWB + (lane >> 4)*16);
        #pragma unroll
        for (int mt = 0; mt < 2; mt++)
            #pragma unroll
            for (int ks = 0; ks < 4; ks++)
                ldsm4(qa[mt][ks][0], qa[mt][ks][1], qa[mt][ks][2], qa[mt][ks][3],
                      qbase + (uint32_t)(mt*16*ROWB + ks*32));
    }

    const uint32_t k_lane = (uint32_t)((((lane & 7) + ((lane >> 4) & 1)*8))*ROWB + ((lane >> 3) & 1)*16);
    const uint32_t v_lane = (uint32_t)((((lane & 7) + ((lane >> 3) & 1)*8))*ROWB + ((lane >> 4) & 1)*16);

    float o[2][8][4];
    #pragma unroll
    for (int mt = 0; mt < 2; mt++)
        #pragma unroll
        for (int nt = 0; nt < 8; nt++)
            #pragma unroll
            for (int c = 0; c < 4; c++) o[mt][nt][c] = 0.f;

    float mrun[2][2] = {{-1e30f, -1e30f}, {-1e30f, -1e30f}};
    float lrun[2][2] = {{0.f, 0.f}, {0.f, 0.f}};

    #pragma unroll 1
    for (int kt = 0; kt < 32; kt++) {
        const int p = kt & 1;
        const uint32_t bufK = sbase + (uint32_t)(QBUF_BYTES + p*BUF_BYTES);
        const uint32_t bufV = bufK + (uint32_t)TILE_BYTES;

        // issue async copy of next K/V tile into the other stage
        if (kt < 31) {
            const uint32_t nbK = sbase + (uint32_t)(QBUF_BYTES + (1-p)*BUF_BYTES);
            const __half* kn = Kg + (size_t)(kt + 1)*4096;
            const __half* vn = Vg + (size_t)(kt + 1)*4096;
            #pragma unroll
            for (int i = 0; i < 4; i++) {
                int r = trow + i*16;
                cpasync16(nbK + (uint32_t)(r*ROWB + tc16*16), kn + r*DH + tc16*8);
                cpasync16(nbK + (uint32_t)(TILE_BYTES + r*ROWB + tc16*16), vn + r*DH + tc16*8);
            }
            cp_commit();
        }

        // ---- S = Q K^T ----
        float s[2][8][4];
        #pragma unroll
        for (int mt = 0; mt < 2; mt++)
            #pragma unroll
            for (int nt = 0; nt < 8; nt++)
                #pragma unroll
                for (int c = 0; c < 4; c++) s[mt][nt][c] = 0.f;

        #pragma unroll
        for (int ks = 0; ks < 4; ks++) {
            #pragma unroll
            for (int np = 0; np < 4; np++) {
                uint32_t a = bufK + k_lane + (uint32_t)(np*16*ROWB + ks*32);
                uint32_t b0, b1, b2, b3;
                ldsm4(b0, b1, b2, b3, a);
                mmah(s[0][np*2  ], qa[0][ks], b0, b1);
                mmah(s[0][np*2+1], qa[0][ks], b2, b3);
                mmah(s[1][np*2  ], qa[1][ks], b0, b1);
                mmah(s[1][np*2+1], qa[1][ks], b2, b3);
            }
        }

        // ---- scale (+ mask), online softmax, pack P to fp16 ----
        uint32_t pa[2][4][4];
        #pragma unroll
        for (int mt = 0; mt < 2; mt++) {
            if (use_mask) {
                int row0 = q0 + warp*32 + mt*16 + gq;
                #pragma unroll
                for (int nt = 0; nt < 8; nt++) {
                    int colb = kt*64 + nt*8 + 2*tg;
                    float2 m0 = *(const float2*)(mask + (size_t)row0     *S_ + colb);
                    float2 m1 = *(const float2*)(mask + (size_t)(row0+8) *S_ + colb);
                    s[mt][nt][0] = s[mt][nt][0]*scale + m0.x;
                    s[mt][nt][1] = s[mt][nt][1]*scale + m0.y;
                    s[mt][nt][2] = s[mt][nt][2]*scale + m1.x;
                    s[mt][nt][3] = s[mt][nt][3]*scale + m1.y;
                }
            } else {
                #pragma unroll
                for (int nt = 0; nt < 8; nt++) {
                    s[mt][nt][0] *= scale; s[mt][nt][1] *= scale;
                    s[mt][nt][2] *= scale; s[mt][nt][3] *= scale;
                }
            }

            float mx0 = fmaxf(s[mt][0][0], s[mt][0][1]);
            float mx1 = fmaxf(s[mt][0][2], s[mt][0][3]);
            #pragma unroll
            for (int nt = 1; nt < 8; nt++) {
                mx0 = fmaxf(mx0, fmaxf(s[mt][nt][0], s[mt][nt][1]));
                mx1 = fmaxf(mx1, fmaxf(s[mt][nt][2], s[mt][nt][3]));
            }
            mx0 = fmaxf(mx0, __shfl_xor_sync(0xffffffffu, mx0, 1));
            mx0 = fmaxf(mx0, __shfl_xor_sync(0xffffffffu, mx0, 2));
            mx1 = fmaxf(mx1, __shfl_xor_sync(0xffffffffu, mx1, 1));
            mx1 = fmaxf(mx1, __shfl_xor_sync(0xffffffffu, mx1, 2));

            float mn0 = fmaxf(mrun[mt][0], mx0), mn1 = fmaxf(mrun[mt][1], mx1);
            float c0 = __expf(mrun[mt][0] - mn0), c1 = __expf(mrun[mt][1] - mn1);
            mrun[mt][0] = mn0; mrun[mt][1] = mn1;

            float su0 = 0.f, su1 = 0.f;
            #pragma unroll
            for (int nt = 0; nt < 8; nt++) {
                float p0 = __expf(s[mt][nt][0] - mn0);
                float p1 = __expf(s[mt][nt][1] - mn0);
                float p2 = __expf(s[mt][nt][2] - mn1);
                float p3 = __expf(s[mt][nt][3] - mn1);
                su0 += p0 + p1; su1 += p2 + p3;
                s[mt][nt][0] = p0; s[mt][nt][1] = p1;
                s[mt][nt][2] = p2; s[mt][nt][3] = p3;
            }
            su0 += __shfl_xor_sync(0xffffffffu, su0, 1);
            su0 += __shfl_xor_sync(0xffffffffu, su0, 2);
            su1 += __shfl_xor_sync(0xffffffffu, su1, 1);
            su1 += __shfl_xor_sync(0xffffffffu, su1, 2);
            lrun[mt][0] = lrun[mt][0]*c0 + su0;
            lrun[mt][1] = lrun[mt][1]*c1 + su1;

            #pragma unroll
            for (int nt = 0; nt < 8; nt++) {
                o[mt][nt][0] *= c0; o[mt][nt][1] *= c0;
                o[mt][nt][2] *= c1; o[mt][nt][3] *= c1;
            }

            // pack P rows into fp16 A-fragments (register-only; same mapping
            // as the QK C-fragment)
            #pragma unroll
            for (int ks = 0; ks < 4; ks++) {
                pa[mt][ks][0] = pk2h(s[mt][2*ks  ][0], s[mt][2*ks  ][1]);
                pa[mt][ks][1] = pk2h(s[mt][2*ks  ][2], s[mt][2*ks  ][3]);
                pa[mt][ks][2] = pk2h(s[mt][2*ks+1][0], s[mt][2*ks+1][1]);
                pa[mt][ks][3] = pk2h(s[mt][2*ks+1][2], s[mt][2*ks+1][3]);
            }
        }

        // ---- O += P @ V ----
        #pragma unroll
        for (int ks = 0; ks < 4; ks++) {
            #pragma unroll
            for (int np = 0; np < 4; np++) {
                uint32_t va = bufV + v_lane + (uint32_t)(ks*16*ROWB + np*32);
                uint32_t h0, h1, h2, h3;
                ldsm4t(h0, h1, h2, h3, va);
                mmah(o[0][np*2  ], pa[0][ks], h0, h1);
                mmah(o[0][np*2+1], pa[0][ks], h2, h3);
                mmah(o[1][np*2  ], pa[1][ks], h0, h1);
                mmah(o[1][np*2+1], pa[1][ks], h2, h3);
            }
        }

        cp_wait0();
        __syncthreads();
    }

    // ---- epilogue: normalize and store ----
    #pragma unroll
    for (int mt = 0; mt < 2; mt++) {
        float i0 = 1.f / lrun[mt][0], i1 = 1.f / lrun[mt][1];
        int r0 = q0 + warp*32 + mt*16 + gq;
        #pragma unroll
        for (int nt = 0; nt < 8; nt++) {
            int cc = nt*8 + 2*tg;
            *(float2*)(Og + (size_t)r0    *DH + cc) = make_float2(o[mt][nt][0]*i0, o[mt][nt][1]*i0);
            *(float2*)(Og + (size_t)(r0+8)*DH + cc) = make_float2(o[mt][nt][2]*i1, o[mt][nt][3]*i1);
        }
    }
}

// ---------------------------------------------------------------------------
extern "C" void kernel_launch(void* const* d_in, const int* in_sizes, int n_in,
                              void* d_out, int out_size)
{
    const float* q    = (const float*)d_in[0];
    const float* k    = (const float*)d_in[1];
    const float* v    = (const float*)d_in[2];
    const float* mask = (const float*)d_in[3];
    const float* Wq   = (const float*)d_in[4];
    const float* bq   = (const float*)d_in[5];
    const float* Wk   = (const float*)d_in[6];
    const float* bk   = (const float*)d_in[7];
    const float* Wv   = (const float*)d_in[8];
    const float* bv   = (const float*)d_in[9];
    float* out = (float*)d_out;

    (void)in_sizes; (void)n_in; (void)out_size;

    cudaFuncSetAttribute(attn_kernel,
                         cudaFuncAttributeMaxDynamicSharedMemorySize,
                         SMEM_ATTN);

    clear_flag_kernel<<<1, 1>>>();
    scan_mask_kernel<<<128, 256>>>(mask);
    proj_kernel<<<dim3(32, 8, 3), 256>>>(q, k, v, Wq, bq, Wk, bk, Wv, bv);
    attn_kernel<<<dim3(16, 16), 128, SMEM_ATTN>>>(mask, out);
}